// round 6
// baseline (speedup 1.0000x reference)
#include <cuda_runtime.h>

// CRF Viterbi decode: B=128, S=512, T=64.
// One CTA per batch, 128 threads = 64 tags x 2 predecessor-segments.
// ONE barrier per time step: per-segment (best,arg) double-buffered in SMEM;
// next step fuses part[i] = fmaxf(seg0[i], seg1[i]) into its reduction.
// Bit-exact with reference: v = (f + trans[i][j]) + part[i];
// first-occurrence argmax (value chain = FMNMX, index = pred-select,
// ascending strict-> combines). Output written as float32.

#define BB 128
#define SS 512
#define TT 64
#define START_TAG 62
#define STOP_TAG 63
#define NEG_INF (-3.402823466e+38f)

__global__ __launch_bounds__(128, 1)
void crf_viterbi1b(const float* __restrict__ feats,
                   const float* __restrict__ trans,
                   const unsigned* __restrict__ candA,
                   const unsigned* __restrict__ candB,
                   float* __restrict__ out)
{
    __shared__ __align__(16) float pbv[2][2][TT];  // [parity][seg][tag] value
    __shared__ int   pba[2][2][TT];                // [parity][seg][tag] arg
    __shared__ float lastp[TT];
    __shared__ unsigned char bp[SS][TT];           // bp[t][j], t>=1, mask-applied
    __shared__ int s_len, s_ptr0, s_clsA, s_clsB;

    const int tid = threadIdx.x;
    const int b   = blockIdx.x;
    const int j   = tid & (TT - 1);
    const int seg = tid >> 6;          // 0 or 1
    const int i0  = seg << 5;          // predecessor range [i0, i0+32)

    float* o = out + b * SS;

    // ---- transitions rows i0..i0+31 of column j into registers
    float tr[32];
#pragma unroll
    for (int u = 0; u < 32; ++u) tr[u] = trans[(i0 + u) * TT + j];

    // ---- identify mask buffer + encoding by content ----------------------
    // bit0: words in {0,1} -> i32; bit1: {0,0x3F800000} -> f32;
    // bit2: bytes in {0,1} -> u8;  bit3: halves in {0,0x3F80} -> bf16
    if (tid == 0) { s_len = 0; s_clsA = 0xF; s_clsB = 0xF; }
    __syncthreads();
    {
        int fa = 0xF, fbc = 0xF;
        for (int s = tid; s < 512; s += 128) {
            unsigned w = candA[s];
            if (w > 1u) fa &= ~1;
            if (w != 0u && w != 0x3F800000u) fa &= ~2;
            if (w & 0xFEFEFEFEu) fa &= ~4;
            { unsigned hi = w >> 16, lo = w & 0xFFFFu;
              if (!((hi==0u||hi==0x3F80u) && (lo==0u||lo==0x3F80u))) fa &= ~8; }
            w = candB[s];
            if (w > 1u) fbc &= ~1;
            if (w != 0u && w != 0x3F800000u) fbc &= ~2;
            if (w & 0xFEFEFEFEu) fbc &= ~4;
            { unsigned hi = w >> 16, lo = w & 0xFFFFu;
              if (!((hi==0u||hi==0x3F80u) && (lo==0u||lo==0x3F80u))) fbc &= ~8; }
        }
        atomicAnd(&s_clsA, fa);
        atomicAnd(&s_clsB, fbc);
    }
    __syncthreads();
    const unsigned* maskw = s_clsA ? candA : candB;
    const int cls = s_clsA ? s_clsA : (s_clsB ? s_clsB : 1);

    // ---- sequence length = nonzero count in mask row b --------------------
    {
        int lsum = 0;
        if (cls & 3) {
            const unsigned* m = maskw + b * SS;
            for (int s = tid; s < SS; s += 128) lsum += (m[s] != 0u);
        } else if (cls & 4) {
            const unsigned char* m = (const unsigned char*)maskw + b * SS;
            for (int s = tid; s < SS; s += 128) lsum += (m[s] != 0);
        } else {
            const unsigned short* m = (const unsigned short*)maskw + b * SS;
            for (int s = tid; s < SS; s += 128) lsum += (m[s] != 0);
        }
        atomicAdd(&s_len, lsum);
    }

    // ---- part0 = feats[b,0,:] + transitions[START_TAG,:] ------------------
    const float* fb = feats + b * SS * TT;
    if (seg == 1) {                        // START_TAG=62 -> seg1, u=30
        float p0v = fb[j] + tr[30];
        pbv[0][0][j] = p0v;                // both segment slots = part0 so
        pbv[0][1][j] = p0v;                // that fmax reconstruction is exact
        lastp[j]     = p0v;                // correct when last_pos == 0
    }
    __syncthreads();
    int len = s_len;
    if (len < 1)  len = 1;
    if (len > SS) len = SS;
    const int last_pos = len - 1;

    // ---- forward recurrence: ONE barrier per step --------------------------
    float fnext = fb[TT + j];
    int buf = 0;
#pragma unroll 1
    for (int t = 1; t < SS; ++t) {
        const float f = fnext;
        if (t + 1 < SS) fnext = fb[(t + 1) * TT + j];

        // reconstruct part[i] = max(seg0[i], seg1[i]) for i in [i0, i0+32)
        float pv[32];
        {
            const float4* q0 = (const float4*)(&pbv[buf][0][i0]);
            const float4* q1 = (const float4*)(&pbv[buf][1][i0]);
#pragma unroll
            for (int q = 0; q < 8; ++q) {
                float4 x = q0[q], y = q1[q];
                pv[4*q+0] = fmaxf(x.x, y.x);
                pv[4*q+1] = fmaxf(x.y, y.y);
                pv[4*q+2] = fmaxf(x.z, y.z);
                pv[4*q+3] = fmaxf(x.w, y.w);
            }
        }

        // 4 chains of 8 (contiguous chunks). Value chain via FMNMX (4-cyc),
        // index via pred-select against the OLD value (first-occurrence ties).
        float b0 = NEG_INF, b1 = NEG_INF, b2 = NEG_INF, b3 = NEG_INF;
        int   a0 = 0,       a1 = 8,       a2 = 16,      a3 = 24;
#pragma unroll
        for (int u = 0; u < 8; ++u) {
            float v0 = (f + tr[u])      + pv[u];
            float v1 = (f + tr[u + 8])  + pv[u + 8];
            float v2 = (f + tr[u + 16]) + pv[u + 16];
            float v3 = (f + tr[u + 24]) + pv[u + 24];
            a0 = (v0 > b0) ? u        : a0;  b0 = fmaxf(b0, v0);
            a1 = (v1 > b1) ? (u + 8)  : a1;  b1 = fmaxf(b1, v1);
            a2 = (v2 > b2) ? (u + 16) : a2;  b2 = fmaxf(b2, v2);
            a3 = (v3 > b3) ? (u + 24) : a3;  b3 = fmaxf(b3, v3);
        }
        // ascending combine; strict > keeps the earliest index on ties
        if (b1 > b0) { b0 = b1; a0 = a1; }
        if (b3 > b2) { b2 = b3; a2 = a3; }
        if (b2 > b0) { b0 = b2; a0 = a2; }

        pbv[buf ^ 1][seg][j] = b0;
        pba[buf ^ 1][seg][j] = i0 + a0;
        __syncthreads();

        // post-barrier shadow: combined (best,arg) for tag j -> bp / lastp
        if (seg == 0) {
            float ob = pbv[buf ^ 1][1][j];
            float best = b0;  int arg = a0;          // seg0 wins ties
            if (ob > best) { best = ob; arg = pba[buf ^ 1][1][j]; }
            bp[t][j] = (unsigned char)((t < len) ? arg : 0);
            if (t == last_pos) lastp[j] = best;
        }
        buf ^= 1;
    }
    __syncthreads();   // publish lastp / bp from the final post-barrier shadow

    // ---- pointer0 = argmax_i( lastp[i] + trans[i][STOP_TAG] ) --------------
    {
        float b0 = NEG_INF; int a0 = 0;
#pragma unroll
        for (int u = 0; u < 32; ++u) {
            float v = lastp[i0 + u] + tr[u];
            a0 = (v > b0) ? u : a0;  b0 = fmaxf(b0, v);
        }
        pbv[0][seg][j] = b0;
        pba[0][seg][j] = i0 + a0;
        __syncthreads();
        if (tid == STOP_TAG) {               // seg0, column STOP_TAG
            float best = pbv[0][0][STOP_TAG];
            int   arg  = pba[0][0][STOP_TAG];
            if (pbv[0][1][STOP_TAG] > best) { arg = pba[0][1][STOP_TAG]; }
            s_ptr0 = arg;
        }
        __syncthreads();
    }

    // ---- backtrack, float output --------------------------------------------
    if (tid == 0) {
        const int p0 = s_ptr0;
        int ptr = p0;
        o[SS - 1] = (float)ptr;
        for (int k = SS - 2; k >= 0; --k) {
            ptr = (k == last_pos) ? p0 : (int)bp[k + 1][ptr];
            o[k] = (float)ptr;
        }
    }
}

extern "C" void kernel_launch(void* const* d_in, const int* in_sizes, int n_in,
                              void* d_out, int out_size) {
    // feats = largest buffer, transitions = smallest; the two leftovers are
    // {mask, tags}, disambiguated by content inside the kernel.
    int fi = 0, ti = 0;
    for (int i = 1; i < n_in; ++i) {
        if (in_sizes[i] > in_sizes[fi]) fi = i;
        if (in_sizes[i] < in_sizes[ti]) ti = i;
    }
    int cA = -1, cB = -1;
    for (int i = 0; i < n_in; ++i) {
        if (i == fi || i == ti) continue;
        if (cA < 0) cA = i; else if (cB < 0) cB = i;
    }
    if (cA < 0) cA = ti;
    if (cB < 0) cB = cA;

    crf_viterbi1b<<<BB, 128>>>((const float*)d_in[fi],
                               (const float*)d_in[ti],
                               (const unsigned*)d_in[cA],
                               (const unsigned*)d_in[cB],
                               (float*)d_out);
}

// round 7
// speedup vs baseline: 1.0339x; 1.0339x over previous
#include <cuda_runtime.h>

// CRF Viterbi decode: B=128, S=512, T=64.
// One CTA per batch, 256 threads = 64 tags x 4 predecessor-segments
// (2 warps per SMSP for latency hiding). Bit-exact with reference:
// v = (f + trans[i][j]) + part[i]; first-occurrence argmax via
// fmax value-chains + pred-select indices, ascending strict-> combines.
// Output written as float32.

#define BB 128
#define SS 512
#define TT 64
#define START_TAG 62
#define STOP_TAG 63
#define NEG_INF (-3.402823466e+38f)
#define NTHR 256

__global__ __launch_bounds__(NTHR, 1)
void crf_viterbi256(const float* __restrict__ feats,
                    const float* __restrict__ trans,
                    const unsigned* __restrict__ candA,
                    const unsigned* __restrict__ candB,
                    float* __restrict__ out)
{
    __shared__ __align__(16) float part[2][TT];
    __shared__ float pbest[4][TT];
    __shared__ int   parg[4][TT];
    __shared__ float lastp[TT];
    __shared__ unsigned char bp[SS][TT];   // bp[t][j], t>=1, mask-applied
    __shared__ int s_len, s_ptr0, s_clsA, s_clsB;

    const int tid = threadIdx.x;
    const int b   = blockIdx.x;
    const int j   = tid & (TT - 1);
    const int seg = tid >> 6;          // 0..3
    const int i0  = seg << 4;          // predecessor range [i0, i0+16)

    float* o = out + b * SS;

    // ---- transitions rows i0..i0+15 of column j into registers
    float tr[16];
#pragma unroll
    for (int u = 0; u < 16; ++u) tr[u] = trans[(i0 + u) * TT + j];

    // ---- identify mask buffer + encoding by content ----------------------
    // bit0: words in {0,1} -> i32; bit1: {0,0x3F800000} -> f32;
    // bit2: bytes in {0,1} -> u8;  bit3: halves in {0,0x3F80} -> bf16
    if (tid == 0) { s_len = 0; s_clsA = 0xF; s_clsB = 0xF; }
    __syncthreads();
    {
        int fa = 0xF, fbc = 0xF;
        for (int s = tid; s < 512; s += NTHR) {
            unsigned w = candA[s];
            if (w > 1u) fa &= ~1;
            if (w != 0u && w != 0x3F800000u) fa &= ~2;
            if (w & 0xFEFEFEFEu) fa &= ~4;
            { unsigned hi = w >> 16, lo = w & 0xFFFFu;
              if (!((hi==0u||hi==0x3F80u) && (lo==0u||lo==0x3F80u))) fa &= ~8; }
            w = candB[s];
            if (w > 1u) fbc &= ~1;
            if (w != 0u && w != 0x3F800000u) fbc &= ~2;
            if (w & 0xFEFEFEFEu) fbc &= ~4;
            { unsigned hi = w >> 16, lo = w & 0xFFFFu;
              if (!((hi==0u||hi==0x3F80u) && (lo==0u||lo==0x3F80u))) fbc &= ~8; }
        }
        atomicAnd(&s_clsA, fa);
        atomicAnd(&s_clsB, fbc);
    }
    __syncthreads();
    const unsigned* maskw = s_clsA ? candA : candB;
    const int cls = s_clsA ? s_clsA : (s_clsB ? s_clsB : 1);

    // ---- sequence length = nonzero count in mask row b --------------------
    {
        int lsum = 0;
        if (cls & 3) {
            const unsigned* m = maskw + b * SS;
            for (int s = tid; s < SS; s += NTHR) lsum += (m[s] != 0u);
        } else if (cls & 4) {
            const unsigned char* m = (const unsigned char*)maskw + b * SS;
            for (int s = tid; s < SS; s += NTHR) lsum += (m[s] != 0);
        } else {
            const unsigned short* m = (const unsigned short*)maskw + b * SS;
            for (int s = tid; s < SS; s += NTHR) lsum += (m[s] != 0);
        }
        atomicAdd(&s_len, lsum);
    }

    // ---- part0 = feats[b,0,:] + transitions[START_TAG,:] ------------------
    const float* fb = feats + b * SS * TT;
    if (seg == 3) {                        // START_TAG=62 -> seg3, u=14
        float p0v = fb[j] + tr[14];
        part[0][j] = p0v;
        lastp[j]   = p0v;                  // correct when last_pos == 0
    }
    __syncthreads();
    int len = s_len;
    if (len < 1)  len = 1;
    if (len > SS) len = SS;
    const int last_pos = len - 1;

    // ---- forward recurrence (2 barriers per step, 4-seg split) -------------
    float fnext = fb[TT + j];
    int buf = 0;
#pragma unroll 1
    for (int t = 1; t < SS; ++t) {
        const float f = fnext;
        if (t + 1 < SS) fnext = fb[(t + 1) * TT + j];

        // vectorized broadcast read of this segment's 16 partition values
        float pv[16];
        {
            const float4* p4 = (const float4*)(&part[buf][i0]);
#pragma unroll
            for (int q = 0; q < 4; ++q) {
                float4 v4 = p4[q];
                pv[4*q+0] = v4.x; pv[4*q+1] = v4.y;
                pv[4*q+2] = v4.z; pv[4*q+3] = v4.w;
            }
        }

        // 4 chains of 4 contiguous preds; value chain FMNMX, index pred-select
        float b0 = NEG_INF, b1 = NEG_INF, b2 = NEG_INF, b3 = NEG_INF;
        int   a0 = 0,       a1 = 4,       a2 = 8,       a3 = 12;
#pragma unroll
        for (int u = 0; u < 4; ++u) {
            float v0 = (f + tr[u])      + pv[u];
            float v1 = (f + tr[u + 4])  + pv[u + 4];
            float v2 = (f + tr[u + 8])  + pv[u + 8];
            float v3 = (f + tr[u + 12]) + pv[u + 12];
            a0 = (v0 > b0) ? u        : a0;  b0 = fmaxf(b0, v0);
            a1 = (v1 > b1) ? (u + 4)  : a1;  b1 = fmaxf(b1, v1);
            a2 = (v2 > b2) ? (u + 8)  : a2;  b2 = fmaxf(b2, v2);
            a3 = (v3 > b3) ? (u + 12) : a3;  b3 = fmaxf(b3, v3);
        }
        // ascending combine; strict > keeps the earliest index on ties
        if (b1 > b0) { b0 = b1; a0 = a1; }
        if (b3 > b2) { b2 = b3; a2 = a3; }
        if (b2 > b0) { b0 = b2; a0 = a2; }

        pbest[seg][j] = b0;
        parg[seg][j]  = i0 + a0;
        __syncthreads();

        if (seg == 0) {
            // combine the 4 segments ascending (seg0's own result = b0/a0)
            float best = b0;  int arg = a0;
            float c1 = pbest[1][j], c2 = pbest[2][j], c3 = pbest[3][j];
            if (c1 > best) { best = c1; arg = parg[1][j]; }
            if (c2 > best) { best = c2; arg = parg[2][j]; }
            if (c3 > best) { best = c3; arg = parg[3][j]; }
            part[buf ^ 1][j] = best;
            bp[t][j] = (unsigned char)((t < len) ? arg : 0);
            if (t == last_pos) lastp[j] = best;
        }
        buf ^= 1;
        __syncthreads();
    }

    // ---- pointer0 = argmax_i( lastp[i] + trans[i][STOP_TAG] ) --------------
    {
        float b0 = NEG_INF; int a0 = 0;
#pragma unroll
        for (int u = 0; u < 16; ++u) {
            float v = lastp[i0 + u] + tr[u];
            a0 = (v > b0) ? u : a0;  b0 = fmaxf(b0, v);
        }
        pbest[seg][j] = b0;
        parg[seg][j]  = i0 + a0;
        __syncthreads();
        if (tid == STOP_TAG) {               // seg0, column STOP_TAG
            float best = pbest[0][STOP_TAG];
            int   arg  = parg[0][STOP_TAG];
            if (pbest[1][STOP_TAG] > best) { best = pbest[1][STOP_TAG]; arg = parg[1][STOP_TAG]; }
            if (pbest[2][STOP_TAG] > best) { best = pbest[2][STOP_TAG]; arg = parg[2][STOP_TAG]; }
            if (pbest[3][STOP_TAG] > best) { arg = parg[3][STOP_TAG]; }
            s_ptr0 = arg;
        }
        __syncthreads();
    }

    // ---- backtrack, float output --------------------------------------------
    if (tid == 0) {
        const int p0 = s_ptr0;
        int ptr = p0;
        o[SS - 1] = (float)ptr;
        for (int k = SS - 2; k >= 0; --k) {
            ptr = (k == last_pos) ? p0 : (int)bp[k + 1][ptr];
            o[k] = (float)ptr;
        }
    }
}

extern "C" void kernel_launch(void* const* d_in, const int* in_sizes, int n_in,
                              void* d_out, int out_size) {
    // feats = largest buffer, transitions = smallest; the two leftovers are
    // {mask, tags}, disambiguated by content inside the kernel.
    int fi = 0, ti = 0;
    for (int i = 1; i < n_in; ++i) {
        if (in_sizes[i] > in_sizes[fi]) fi = i;
        if (in_sizes[i] < in_sizes[ti]) ti = i;
    }
    int cA = -1, cB = -1;
    for (int i = 0; i < n_in; ++i) {
        if (i == fi || i == ti) continue;
        if (cA < 0) cA = i; else if (cB < 0) cB = i;
    }
    if (cA < 0) cA = ti;
    if (cB < 0) cB = cA;

    crf_viterbi256<<<BB, NTHR>>>((const float*)d_in[fi],
                                 (const float*)d_in[ti],
                                 (const unsigned*)d_in[cA],
                                 (const unsigned*)d_in[cB],
                                 (float*)d_out);
}

// round 8
// speedup vs baseline: 1.1610x; 1.1229x over previous
#include <cuda_runtime.h>

// CRF Viterbi decode: B=128, S=512, T=64.
// One CTA per batch, 128 threads. Warp w owns tags 16w..16w+15;
// lanes 0-15 = predecessor seg [0,32), lanes 16-31 = seg [32,64).
// ONE __syncthreads per step; cross-segment combine via __shfl_xor(16).
// ftr = f + tr precomputed before the barrier (off the critical path).
// Bit-exact with reference: v = (f + trans[i][j]) + part[i];
// first-occurrence argmax (fmax value chains, pred-select indices,
// ascending strict-> combines, seg0 wins ties). Output float32.

#define BB 128
#define SS 512
#define TT 64
#define START_TAG 62
#define STOP_TAG 63
#define NEG_INF (-3.402823466e+38f)
#define NTHR 128

__global__ __launch_bounds__(NTHR, 1)
void crf_viterbi_shfl(const float* __restrict__ feats,
                      const float* __restrict__ trans,
                      const unsigned* __restrict__ candA,
                      const unsigned* __restrict__ candB,
                      float* __restrict__ out)
{
    __shared__ __align__(16) float part[2][TT];
    __shared__ float lastp[TT];
    __shared__ unsigned char bp[SS][TT];   // bp[t][j], t>=1, mask-applied
    __shared__ int s_len, s_ptr0, s_clsA, s_clsB;

    const int tid  = threadIdx.x;
    const int b    = blockIdx.x;
    const int warp = tid >> 5;
    const int lane = tid & 31;
    const int tag  = (warp << 4) | (lane & 15);
    const int seg  = lane >> 4;          // 0 or 1
    const int i0   = seg << 5;           // predecessor range [i0, i0+32)

    float* o = out + b * SS;

    // ---- transitions rows i0..i0+31 of column `tag` into registers
    float tr[32];
#pragma unroll
    for (int u = 0; u < 32; ++u) tr[u] = trans[(i0 + u) * TT + tag];

    // ---- identify mask buffer + encoding by content ----------------------
    // bit0: words in {0,1} -> i32; bit1: {0,0x3F800000} -> f32;
    // bit2: bytes in {0,1} -> u8;  bit3: halves in {0,0x3F80} -> bf16
    if (tid == 0) { s_len = 0; s_clsA = 0xF; s_clsB = 0xF; }
    __syncthreads();
    {
        int fa = 0xF, fbc = 0xF;
        for (int s = tid; s < 512; s += NTHR) {
            unsigned w = candA[s];
            if (w > 1u) fa &= ~1;
            if (w != 0u && w != 0x3F800000u) fa &= ~2;
            if (w & 0xFEFEFEFEu) fa &= ~4;
            { unsigned hi = w >> 16, lo = w & 0xFFFFu;
              if (!((hi==0u||hi==0x3F80u) && (lo==0u||lo==0x3F80u))) fa &= ~8; }
            w = candB[s];
            if (w > 1u) fbc &= ~1;
            if (w != 0u && w != 0x3F800000u) fbc &= ~2;
            if (w & 0xFEFEFEFEu) fbc &= ~4;
            { unsigned hi = w >> 16, lo = w & 0xFFFFu;
              if (!((hi==0u||hi==0x3F80u) && (lo==0u||lo==0x3F80u))) fbc &= ~8; }
        }
        atomicAnd(&s_clsA, fa);
        atomicAnd(&s_clsB, fbc);
    }
    __syncthreads();
    const unsigned* maskw = s_clsA ? candA : candB;
    const int cls = s_clsA ? s_clsA : (s_clsB ? s_clsB : 1);

    // ---- sequence length = nonzero count in mask row b --------------------
    {
        int lsum = 0;
        if (cls & 3) {
            const unsigned* m = maskw + b * SS;
            for (int s = tid; s < SS; s += NTHR) lsum += (m[s] != 0u);
        } else if (cls & 4) {
            const unsigned char* m = (const unsigned char*)maskw + b * SS;
            for (int s = tid; s < SS; s += NTHR) lsum += (m[s] != 0);
        } else {
            const unsigned short* m = (const unsigned short*)maskw + b * SS;
            for (int s = tid; s < SS; s += NTHR) lsum += (m[s] != 0);
        }
        atomicAdd(&s_len, lsum);
    }

    // ---- part0 = feats[b,0,:] + transitions[START_TAG,:] ------------------
    const float* fb = feats + b * SS * TT;
    if (seg == 1) {                        // START row 62 = seg1, u = 30
        float p0v = fb[tag] + tr[30];
        part[0][tag] = p0v;
        lastp[tag]   = p0v;                // correct when last_pos == 0
    }
    __syncthreads();
    int len = s_len;
    if (len < 1)  len = 1;
    if (len > SS) len = SS;
    const int last_pos = len - 1;

    // ---- ftr for t = 1, prefetch feat for t = 2 ----------------------------
    float ftr[32];
    {
        float f1 = fb[TT + tag];
#pragma unroll
        for (int u = 0; u < 32; ++u) ftr[u] = f1 + tr[u];
    }
    float fnext = fb[2 * TT + tag];

    // ---- forward recurrence: ONE barrier per step ---------------------------
    int buf = 0;
#pragma unroll 1
    for (int t = 1; t < SS; ++t) {
        // read this segment's 32 partition values (vectorized broadcast)
        float pv[32];
        {
            const float4* p4 = (const float4*)(&part[buf][i0]);
#pragma unroll
            for (int q = 0; q < 8; ++q) {
                float4 v4 = p4[q];
                pv[4*q+0] = v4.x; pv[4*q+1] = v4.y;
                pv[4*q+2] = v4.z; pv[4*q+3] = v4.w;
            }
        }

        // 4 chains of 8 contiguous preds; value chain FMNMX, index pred-select
        float b0 = NEG_INF, b1 = NEG_INF, b2 = NEG_INF, b3 = NEG_INF;
        int   a0 = 0,       a1 = 8,       a2 = 16,      a3 = 24;
#pragma unroll
        for (int u = 0; u < 8; ++u) {
            float v0 = ftr[u]      + pv[u];
            float v1 = ftr[u + 8]  + pv[u + 8];
            float v2 = ftr[u + 16] + pv[u + 16];
            float v3 = ftr[u + 24] + pv[u + 24];
            a0 = (v0 > b0) ? u        : a0;  b0 = fmaxf(b0, v0);
            a1 = (v1 > b1) ? (u + 8)  : a1;  b1 = fmaxf(b1, v1);
            a2 = (v2 > b2) ? (u + 16) : a2;  b2 = fmaxf(b2, v2);
            a3 = (v3 > b3) ? (u + 24) : a3;  b3 = fmaxf(b3, v3);
        }
        // ascending combine; strict > keeps the earliest index on ties
        if (b1 > b0) { b0 = b1; a0 = a1; }
        if (b3 > b2) { b2 = b3; a2 = a3; }
        if (b2 > b0) { b0 = b2; a0 = a2; }
        int ag = i0 + a0;

        // cross-segment combine inside the warp (lanes l <-> l^16)
        float bo = __shfl_xor_sync(0xffffffffu, b0, 16);
        int   ao = __shfl_xor_sync(0xffffffffu, ag, 16);

        if (seg == 0) {
            float best = b0;  int arg = ag;      // seg0 wins ties
            if (bo > best) { best = bo; arg = ao; }
            part[buf ^ 1][tag] = best;
            bp[t][tag] = (unsigned char)((t < len) ? arg : 0);
            if (t == last_pos) lastp[tag] = best;
        }

        // build ftr for step t+1 BEFORE the barrier (hidden behind arrive skew)
        {
            float f = fnext;
            if (t + 2 < SS) fnext = fb[(t + 2) * TT + tag];
#pragma unroll
            for (int u = 0; u < 32; ++u) ftr[u] = f + tr[u];
        }

        buf ^= 1;
        __syncthreads();
    }

    // ---- pointer0 = argmax_i( lastp[i] + trans[i][STOP_TAG] ) --------------
    {
        float b0 = NEG_INF, b1 = NEG_INF, b2 = NEG_INF, b3 = NEG_INF;
        int   a0 = 0,       a1 = 8,       a2 = 16,      a3 = 24;
#pragma unroll
        for (int u = 0; u < 8; ++u) {
            float v0 = lastp[i0 + u]      + tr[u];
            float v1 = lastp[i0 + u + 8]  + tr[u + 8];
            float v2 = lastp[i0 + u + 16] + tr[u + 16];
            float v3 = lastp[i0 + u + 24] + tr[u + 24];
            a0 = (v0 > b0) ? u        : a0;  b0 = fmaxf(b0, v0);
            a1 = (v1 > b1) ? (u + 8)  : a1;  b1 = fmaxf(b1, v1);
            a2 = (v2 > b2) ? (u + 16) : a2;  b2 = fmaxf(b2, v2);
            a3 = (v3 > b3) ? (u + 24) : a3;  b3 = fmaxf(b3, v3);
        }
        if (b1 > b0) { b0 = b1; a0 = a1; }
        if (b3 > b2) { b2 = b3; a2 = a3; }
        if (b2 > b0) { b0 = b2; a0 = a2; }
        int ag = i0 + a0;

        float bo = __shfl_xor_sync(0xffffffffu, b0, 16);
        int   ao = __shfl_xor_sync(0xffffffffu, ag, 16);
        if (seg == 0 && tag == STOP_TAG) {
            int arg = ag;
            if (bo > b0) arg = ao;
            s_ptr0 = arg;
        }
        __syncthreads();
    }

    // ---- backtrack, float output ---------------------------------------------
    if (tid == 0) {
        const int p0 = s_ptr0;
        int ptr = p0;
        o[SS - 1] = (float)ptr;
        for (int k = SS - 2; k >= 0; --k) {
            ptr = (k == last_pos) ? p0 : (int)bp[k + 1][ptr];
            o[k] = (float)ptr;
        }
    }
}

extern "C" void kernel_launch(void* const* d_in, const int* in_sizes, int n_in,
                              void* d_out, int out_size) {
    // feats = largest buffer, transitions = smallest; the two leftovers are
    // {mask, tags}, disambiguated by content inside the kernel.
    int fi = 0, ti = 0;
    for (int i = 1; i < n_in; ++i) {
        if (in_sizes[i] > in_sizes[fi]) fi = i;
        if (in_sizes[i] < in_sizes[ti]) ti = i;
    }
    int cA = -1, cB = -1;
    for (int i = 0; i < n_in; ++i) {
        if (i == fi || i == ti) continue;
        if (cA < 0) cA = i; else if (cB < 0) cB = i;
    }
    if (cA < 0) cA = ti;
    if (cB < 0) cB = cA;

    crf_viterbi_shfl<<<BB, NTHR>>>((const float*)d_in[fi],
                                   (const float*)d_in[ti],
                                   (const unsigned*)d_in[cA],
                                   (const unsigned*)d_in[cB],
                                   (float*)d_out);
}